// round 10
// baseline (speedup 1.0000x reference)
#include <cuda_runtime.h>
#include <cuda_bf16.h>
#include <math.h>
#include <stdint.h>

// ---------------------------------------------------------------------------
// CircleLoss forward, B=8192, D=1024, N_IDS=512 — mma.sync bf16 edition, v4.
//  1) normalize (fp32) -> bf16 matrix g_xb; target histogram
//  2) triangular 128x128-tile HMMA GEMM (2-D grid, early exit), 3-stage
//     cp.async pipeline. Epilogue, from the register accumulators:
//       negatives (different target): exp(relu(s+.25)(s-.25)*64 - 60), fp32
//         fixed-max LSE (safe for all s in [-1,1])
//       positives (same target, i!=j): exp(lp - 128) in fp64 (lp in [-4,252]
//         -> e^-132..e^124, unconditionally safe, no online max needed)
//     row partials + mirrored col partials, deterministic (no float atomics).
//  3) rowlse: loss = softplus(60 + log(sum_n) + 128 + log(sum_p)); validity
//     from histogram (cnt>=2 && cnt<NB).  4) deterministic mean.
// ---------------------------------------------------------------------------

#define NB 8192
#define ND 1024
#define NT 64               // 8192 / 128 tiles
#define STAGE_BYTES 10240u  // 128 rows * 80 B (40 halves, padded)

__device__ __nv_bfloat16 g_xb[NB * ND];     // 16 MB (L2-resident)
__device__ float  g_part_n[NB * NT];        // 2 MB
__device__ double g_part_p[NB * NT];        // 4 MB
__device__ float  g_loss[NB];
__device__ int    g_tgt[NB];
__device__ int    g_hist[512];
__device__ int    g_is64;

// ---------------- PTX helpers ----------------------------------------------
__device__ __forceinline__ uint32_t smem_u32(const void* p) {
    uint32_t a;
    asm("{ .reg .u64 t; cvta.to.shared.u64 t, %1; cvt.u32.u64 %0, t; }"
        : "=r"(a) : "l"(p));
    return a;
}
__device__ __forceinline__ void cp16(uint32_t dst, const void* src) {
    asm volatile("cp.async.cg.shared.global [%0], [%1], 16;"
                 :: "r"(dst), "l"(src) : "memory");
}
#define CP_COMMIT() asm volatile("cp.async.commit_group;" ::: "memory")
#define CP_WAIT(n)  asm volatile("cp.async.wait_group %0;" :: "n"(n) : "memory")

__device__ __forceinline__ void ldm_x4(uint32_t a, uint32_t& r0, uint32_t& r1,
                                       uint32_t& r2, uint32_t& r3) {
    asm volatile("ldmatrix.sync.aligned.m8n8.x4.shared.b16 {%0,%1,%2,%3}, [%4];"
                 : "=r"(r0), "=r"(r1), "=r"(r2), "=r"(r3) : "r"(a));
}
__device__ __forceinline__ void ldm_x2(uint32_t a, uint32_t& r0, uint32_t& r1) {
    asm volatile("ldmatrix.sync.aligned.m8n8.x2.shared.b16 {%0,%1}, [%2];"
                 : "=r"(r0), "=r"(r1) : "r"(a));
}
__device__ __forceinline__ void mma16816(float* d, const uint32_t* a,
                                         const uint32_t* b) {
    asm volatile(
        "mma.sync.aligned.m16n8k16.row.col.f32.bf16.bf16.f32 "
        "{%0,%1,%2,%3}, {%4,%5,%6,%7}, {%8,%9}, {%0,%1,%2,%3};"
        : "+f"(d[0]), "+f"(d[1]), "+f"(d[2]), "+f"(d[3])
        : "r"(a[0]), "r"(a[1]), "r"(a[2]), "r"(a[3]), "r"(b[0]), "r"(b[1]));
}

// ---------------------------------------------------------------------------
// Kernel 0: zero histogram; detect targets dtype (int64 LE has odd words 0).
// ---------------------------------------------------------------------------
__global__ void detect_k(const int* __restrict__ tg32) {
    int tid = threadIdx.x;
    if (tid < 512) g_hist[tid] = 0;
    if (tid == 0) {
        int odd_or = 0;
        #pragma unroll
        for (int i = 1; i < 128; i += 2) odd_or |= tg32[i];
        g_is64 = (odd_or == 0) ? 1 : 0;
    }
}

// ---------------------------------------------------------------------------
// Kernel 1: fp32 normalize -> bf16; targets -> int32; histogram.
// ---------------------------------------------------------------------------
__global__ __launch_bounds__(256) void normalize_k(const float* __restrict__ x,
                                                   const void* __restrict__ tg) {
    int row = blockIdx.x;
    int tid = threadIdx.x;
    float4 v = reinterpret_cast<const float4*>(x)[row * (ND / 4) + tid];
    float ss = v.x * v.x + v.y * v.y + v.z * v.z + v.w * v.w;
    #pragma unroll
    for (int o = 16; o; o >>= 1) ss += __shfl_xor_sync(0xffffffffu, ss, o);
    __shared__ float sh[8];
    if ((tid & 31) == 0) sh[tid >> 5] = ss;
    __syncthreads();
    if (tid < 32) {
        float t = (tid < 8) ? sh[tid] : 0.f;
        #pragma unroll
        for (int o = 4; o; o >>= 1) t += __shfl_xor_sync(0xffffffffu, t, o);
        if (tid == 0) sh[0] = t;
    }
    __syncthreads();
    float inv = 1.0f / fmaxf(sqrtf(sh[0]), 1e-12f);
    __nv_bfloat162 p0 = __floats2bfloat162_rn(v.x * inv, v.y * inv);
    __nv_bfloat162 p1 = __floats2bfloat162_rn(v.z * inv, v.w * inv);
    __nv_bfloat162* dst =
        reinterpret_cast<__nv_bfloat162*>(g_xb + (size_t)row * ND + tid * 4);
    dst[0] = p0; dst[1] = p1;
    if (tid == 0) {
        int t = g_is64 ? (int)((const long long*)tg)[row]
                       : ((const int*)tg)[row];
        g_tgt[row] = t;
        if ((unsigned)t < 512u) atomicAdd(&g_hist[t], 1);
    }
}

// ---------------------------------------------------------------------------
// Kernel 2: HMMA triangular GEMM + fused pos/neg LSE epilogue.
// 2-D grid (bx>=by live). CTA tile 128x128, 8 warps (2x4), warp tile 64x32,
// BK=32, 3-stage cp.async pipeline, one barrier per k-iteration.
// ---------------------------------------------------------------------------
__global__ __launch_bounds__(256) void gemm_k() {
    int bx = blockIdx.x, by = blockIdx.y;
    if (bx < by) return;
    const int rm = by * 128, cn = bx * 128;

    extern __shared__ char smem[];
    __shared__ int sh_tr[128], sh_tc[128];

    int tid = threadIdx.x, lane = tid & 31, wid = tid >> 5;
    int warp_m = wid >> 2, warp_n = wid & 3;

    if (tid < 128) sh_tr[tid] = g_tgt[rm + tid];
    else           sh_tc[tid - 128] = g_tgt[cn + tid - 128];

    const __nv_bfloat16* gA = g_xb + (size_t)rm * ND;
    const __nv_bfloat16* gB = g_xb + (size_t)cn * ND;
    uint32_t aSm = smem_u32(smem);                       // A stages: 3 * 10240
    uint32_t bSm = aSm + 3 * STAGE_BYTES;                // B stages: 3 * 10240

    int ch0 = tid * 2, ch1 = tid * 2 + 1;
    int cr0 = ch0 >> 2, cs0 = ch0 & 3, cr1 = ch1 >> 2, cs1 = ch1 & 3;
    uint32_t oA0 = (uint32_t)(cr0 * 80 + cs0 * 16), oA1 = (uint32_t)(cr1 * 80 + cs1 * 16);
    const __nv_bfloat16* pA0 = gA + (size_t)cr0 * ND + cs0 * 8;
    const __nv_bfloat16* pA1 = gA + (size_t)cr1 * ND + cs1 * 8;
    const __nv_bfloat16* pB0 = gB + (size_t)cr0 * ND + cs0 * 8;
    const __nv_bfloat16* pB1 = gB + (size_t)cr1 * ND + cs1 * 8;

    float acc[4][4][4];
    #pragma unroll
    for (int i = 0; i < 4; i++)
        #pragma unroll
        for (int j = 0; j < 4; j++)
            #pragma unroll
            for (int e = 0; e < 4; e++) acc[i][j][e] = 0.f;

    uint32_t aF = aSm + ((warp_m * 64 + (lane & 15)) * 40 + (lane >> 4) * 8) * 2;
    uint32_t bF = bSm + ((warp_n * 32 + ((lane & 15) & 7)) * 40 +
                         (((lane & 15) >> 3)) * 8) * 2;

    #pragma unroll
    for (int s = 0; s < 2; s++) {
        uint32_t so = s * STAGE_BYTES;
        cp16(aSm + so + oA0, pA0 + s * 32);
        cp16(aSm + so + oA1, pA1 + s * 32);
        cp16(bSm + so + oA0, pB0 + s * 32);
        cp16(bSm + so + oA1, pB1 + s * 32);
        CP_COMMIT();
    }

    int sc = 0;  // kc % 3
    for (int kc = 0; kc < 32; kc++) {
        if (kc < 30) { CP_WAIT(1); } else { CP_WAIT(0); }
        __syncthreads();
        if (kc + 2 < 32) {
            int sn = sc + 2; if (sn >= 3) sn -= 3;
            uint32_t so = (uint32_t)sn * STAGE_BYTES;
            cp16(aSm + so + oA0, pA0 + (kc + 2) * 32);
            cp16(aSm + so + oA1, pA1 + (kc + 2) * 32);
            cp16(bSm + so + oA0, pB0 + (kc + 2) * 32);
            cp16(bSm + so + oA1, pB1 + (kc + 2) * 32);
            CP_COMMIT();
        }
        uint32_t bo = (uint32_t)sc * STAGE_BYTES;
        #pragma unroll
        for (int kk = 0; kk < 2; kk++) {
            uint32_t af[4][4], bf2[4][2];
            #pragma unroll
            for (int am = 0; am < 4; am++)
                ldm_x4(aF + bo + am * 1280u + kk * 32u,
                       af[am][0], af[am][1], af[am][2], af[am][3]);
            #pragma unroll
            for (int an = 0; an < 4; an++)
                ldm_x2(bF + bo + an * 640u + kk * 32u, bf2[an][0], bf2[an][1]);
            #pragma unroll
            for (int am = 0; am < 4; am++)
                #pragma unroll
                for (int an = 0; an < 4; an++)
                    mma16816(acc[am][an], af[am], bf2[an]);
        }
        if (++sc == 3) sc = 0;
    }
    __syncthreads();   // all ldmatrix done before smem reuse below

    bool diag = (bx == by);
    int lr_base = warp_m * 64;
    int lc_base = warp_n * 32;

    // smem reuse layout (dynamic): [0,2048) rowbuf_f, [2048,3072) colbuf_f,
    // [3072,7168) rowbuf_d, [7168,9216) colbuf_d
    float*  rowbuf_f = reinterpret_cast<float*>(smem);           // [4][128]
    float*  colbuf_f = reinterpret_cast<float*>(smem + 2048);    // [2][128]
    double* rowbuf_d = reinterpret_cast<double*>(smem + 3072);   // [4][128]
    double* colbuf_d = reinterpret_cast<double*>(smem + 7168);   // [2][128]

    // ---- pass 1: negatives (different target), fp32 fixed-max 60 ----------
    {
        float rsum[4][2], csum[4][2];
        #pragma unroll
        for (int a = 0; a < 4; a++) {
            rsum[a][0] = rsum[a][1] = 0.f;
            csum[a][0] = csum[a][1] = 0.f;
        }
        #pragma unroll
        for (int am = 0; am < 4; am++) {
            int r0 = lr_base + am * 16 + (lane >> 2);
            #pragma unroll
            for (int an = 0; an < 4; an++) {
                int c0 = lc_base + an * 8 + (lane & 3) * 2;
                #pragma unroll
                for (int e = 0; e < 4; e++) {
                    int rr = r0 + (e >> 1) * 8;
                    int cc = c0 + (e & 1);
                    float s = acc[am][an][e];
                    float ex = __expf(fmaxf(s + 0.25f, 0.f) * (s - 0.25f) * 64.f - 60.f);
                    if (sh_tr[rr] == sh_tc[cc]) ex = 0.f;  // same target: not a neg
                    rsum[am][e >> 1] += ex;
                    csum[an][e & 1] += ex;
                }
            }
        }
        #pragma unroll
        for (int am = 0; am < 4; am++)
            #pragma unroll
            for (int t = 0; t < 2; t++) {
                float v = rsum[am][t];
                v += __shfl_xor_sync(0xffffffffu, v, 1);
                v += __shfl_xor_sync(0xffffffffu, v, 2);
                if ((lane & 3) == 0)
                    rowbuf_f[warp_n * 128 + lr_base + am * 16 + t * 8 + (lane >> 2)] = v;
            }
        #pragma unroll
        for (int an = 0; an < 4; an++)
            #pragma unroll
            for (int c = 0; c < 2; c++) {
                float v = csum[an][c];
                v += __shfl_xor_sync(0xffffffffu, v, 4);
                v += __shfl_xor_sync(0xffffffffu, v, 8);
                v += __shfl_xor_sync(0xffffffffu, v, 16);
                if (lane < 4)
                    colbuf_f[warp_m * 128 + lc_base + an * 8 + lane * 2 + c] = v;
            }
    }

    // ---- pass 2: positives (same target, i!=j), fp64 fixed-shift 128 ------
    {
        double rp[4][2], cp[4][2];
        #pragma unroll
        for (int a = 0; a < 4; a++) {
            rp[a][0] = rp[a][1] = 0.0;
            cp[a][0] = cp[a][1] = 0.0;
        }
        #pragma unroll
        for (int am = 0; am < 4; am++) {
            int r0 = lr_base + am * 16 + (lane >> 2);
            #pragma unroll
            for (int an = 0; an < 4; an++) {
                int c0 = lc_base + an * 8 + (lane & 3) * 2;
                #pragma unroll
                for (int e = 0; e < 4; e++) {
                    int rr = r0 + (e >> 1) * 8;
                    int cc = c0 + (e & 1);
                    if (sh_tr[rr] == sh_tc[cc] && !(diag && rr == cc)) {
                        float s = acc[am][an][e];
                        float lp = -fmaxf(1.25f - s, 0.f) * (s - 0.75f) * 64.f;
                        double ev = exp((double)lp - 128.0);
                        rp[am][e >> 1] += ev;
                        cp[an][e & 1] += ev;
                    }
                }
            }
        }
        #pragma unroll
        for (int am = 0; am < 4; am++)
            #pragma unroll
            for (int t = 0; t < 2; t++) {
                double v = rp[am][t];
                v += __shfl_xor_sync(0xffffffffu, v, 1);
                v += __shfl_xor_sync(0xffffffffu, v, 2);
                if ((lane & 3) == 0)
                    rowbuf_d[warp_n * 128 + lr_base + am * 16 + t * 8 + (lane >> 2)] = v;
            }
        #pragma unroll
        for (int an = 0; an < 4; an++)
            #pragma unroll
            for (int c = 0; c < 2; c++) {
                double v = cp[an][c];
                v += __shfl_xor_sync(0xffffffffu, v, 4);
                v += __shfl_xor_sync(0xffffffffu, v, 8);
                v += __shfl_xor_sync(0xffffffffu, v, 16);
                if (lane < 4)
                    colbuf_d[warp_m * 128 + lc_base + an * 8 + lane * 2 + c] = v;
            }
    }
    __syncthreads();
    if (tid < 128) {
        float s = rowbuf_f[tid] + rowbuf_f[128 + tid] +
                  rowbuf_f[256 + tid] + rowbuf_f[384 + tid];
        g_part_n[(size_t)(rm + tid) * NT + bx] = s;
        double sd = rowbuf_d[tid] + rowbuf_d[128 + tid] +
                    rowbuf_d[256 + tid] + rowbuf_d[384 + tid];
        g_part_p[(size_t)(rm + tid) * NT + bx] = sd;
        if (bx > by) {
            g_part_n[(size_t)(cn + tid) * NT + by] = colbuf_f[tid] + colbuf_f[128 + tid];
            g_part_p[(size_t)(cn + tid) * NT + by] = colbuf_d[tid] + colbuf_d[128 + tid];
        }
    }
}

// ---------------------------------------------------------------------------
// Kernel 3: per-row combine (deterministic fixed-order), softplus, validity.
// ---------------------------------------------------------------------------
__global__ __launch_bounds__(256) void rowlse_k() {
    int row = blockIdx.x * 256 + threadIdx.x;
    float sn = 0.f;
    #pragma unroll 16
    for (int k = 0; k < NT; k++) sn += g_part_n[(size_t)row * NT + k];
    double sp = 0.0;
    #pragma unroll 8
    for (int k = 0; k < NT; k++) sp += g_part_p[(size_t)row * NT + k];

    int t = g_tgt[row];
    int c = ((unsigned)t < 512u) ? g_hist[t] : 0;
    int valid = (c >= 2) && (c < NB);

    float loss = 0.f;
    if (valid) {
        sn = fmaxf(sn, 1e-37f);
        float lse_n = 60.f + logf(sn);
        float lse_p = 128.f + (float)log(sp);
        float x = lse_n + lse_p;
        loss = fmaxf(x, 0.f) + log1pf(expf(-fabsf(x)));
    }
    g_loss[row] = valid ? loss : 0.f;
    // reuse g_tgt slot? no — keep validity implicit via hist in finalize
}

// ---------------------------------------------------------------------------
// Kernel 4: deterministic final reduction (validity recomputed from hist).
// ---------------------------------------------------------------------------
__global__ __launch_bounds__(1024) void finalize_k(float* __restrict__ out) {
    __shared__ float sh_s[1024];
    __shared__ int sh_c[1024];
    int tid = threadIdx.x;
    float t = 0.f;
    int c = 0;
    for (int r = tid; r < NB; r += 1024) {
        t += g_loss[r];
        int tv = g_tgt[r];
        int cnt = ((unsigned)tv < 512u) ? g_hist[tv] : 0;
        c += ((cnt >= 2) && (cnt < NB)) ? 1 : 0;
    }
    sh_s[tid] = t; sh_c[tid] = c;
    __syncthreads();
    for (int off = 512; off > 0; off >>= 1) {
        if (tid < off) {
            sh_s[tid] += sh_s[tid + off];
            sh_c[tid] += sh_c[tid + off];
        }
        __syncthreads();
    }
    if (tid == 0) {
        int cnt = sh_c[0] > 1 ? sh_c[0] : 1;
        out[0] = sh_s[0] / (float)cnt;
    }
}

// ---------------------------------------------------------------------------
extern "C" void kernel_launch(void* const* d_in, const int* in_sizes, int n_in,
                              void* d_out, int out_size) {
    const float* x = (const float*)d_in[0];
    const void* tg = d_in[1];
    float* out = (float*)d_out;

    cudaFuncSetAttribute(gemm_k, cudaFuncAttributeMaxDynamicSharedMemorySize, 61440);

    detect_k<<<1, 512>>>((const int*)tg);
    normalize_k<<<NB, 256>>>(x, tg);
    gemm_k<<<dim3(NT, NT), 256, 61440>>>();
    rowlse_k<<<NB / 256, 256>>>();
    finalize_k<<<1, 1024>>>(out);
}

// round 11
// speedup vs baseline: 1.2865x; 1.2865x over previous
#include <cuda_runtime.h>
#include <cuda_bf16.h>
#include <math.h>
#include <stdint.h>

// ---------------------------------------------------------------------------
// CircleLoss forward, B=8192, D=1024, N_IDS=512 — mma.sync bf16 edition, v5.
//  1) normalize (fp32) -> bf16 g_xb; target histogram
//  2) triangular 128x128-tile HMMA GEMM (2-D grid, early exit), 3-stage
//     cp.async pipeline. Fused epilogue (all fp32):
//       negatives (different target): exp(l - 60) fixed-max (safe: l<=60)
//       positives (same target, i!=j): exact two-pass LSE — pre-pass computes
//         per-(row,tile)/(col,tile) maxima, then exp(lp - m). Robust for any
//         input, no fp64.
//     row partials + mirrored col partials, deterministic.
//  3) rowlse (warp per row): merge 64 (m,s) pairs online + neg sums ->
//     loss = softplus(60 + log(sum_n) + lse_p).  4) deterministic mean.
// ---------------------------------------------------------------------------

#define NB 8192
#define ND 1024
#define NT 64               // 8192 / 128 tiles
#define STAGE_BYTES 10240u  // 128 rows * 80 B (40 halves, padded)
#define NEG_INF (-1e30f)

__device__ __nv_bfloat16 g_xb[NB * ND];     // 16 MB (L2-resident)
__device__ float g_part_n[NB * NT];         // 2 MB  neg exp-sums
__device__ float g_part_pm[NB * NT];        // 2 MB  pos max per (row,tile)
__device__ float g_part_ps[NB * NT];        // 2 MB  pos exp-sum rel. to max
__device__ float g_loss[NB];
__device__ int   g_tgt[NB];
__device__ int   g_hist[512];
__device__ int   g_is64;

// ---------------- PTX helpers ----------------------------------------------
__device__ __forceinline__ uint32_t smem_u32(const void* p) {
    uint32_t a;
    asm("{ .reg .u64 t; cvta.to.shared.u64 t, %1; cvt.u32.u64 %0, t; }"
        : "=r"(a) : "l"(p));
    return a;
}
__device__ __forceinline__ void cp16(uint32_t dst, const void* src) {
    asm volatile("cp.async.cg.shared.global [%0], [%1], 16;"
                 :: "r"(dst), "l"(src) : "memory");
}
#define CP_COMMIT() asm volatile("cp.async.commit_group;" ::: "memory")
#define CP_WAIT(n)  asm volatile("cp.async.wait_group %0;" :: "n"(n) : "memory")

__device__ __forceinline__ void ldm_x4(uint32_t a, uint32_t& r0, uint32_t& r1,
                                       uint32_t& r2, uint32_t& r3) {
    asm volatile("ldmatrix.sync.aligned.m8n8.x4.shared.b16 {%0,%1,%2,%3}, [%4];"
                 : "=r"(r0), "=r"(r1), "=r"(r2), "=r"(r3) : "r"(a));
}
__device__ __forceinline__ void ldm_x2(uint32_t a, uint32_t& r0, uint32_t& r1) {
    asm volatile("ldmatrix.sync.aligned.m8n8.x2.shared.b16 {%0,%1}, [%2];"
                 : "=r"(r0), "=r"(r1) : "r"(a));
}
__device__ __forceinline__ void mma16816(float* d, const uint32_t* a,
                                         const uint32_t* b) {
    asm volatile(
        "mma.sync.aligned.m16n8k16.row.col.f32.bf16.bf16.f32 "
        "{%0,%1,%2,%3}, {%4,%5,%6,%7}, {%8,%9}, {%0,%1,%2,%3};"
        : "+f"(d[0]), "+f"(d[1]), "+f"(d[2]), "+f"(d[3])
        : "r"(a[0]), "r"(a[1]), "r"(a[2]), "r"(a[3]), "r"(b[0]), "r"(b[1]));
}

// ---------------------------------------------------------------------------
// Kernel 0: zero histogram; detect targets dtype (int64 LE has odd words 0).
// ---------------------------------------------------------------------------
__global__ void detect_k(const int* __restrict__ tg32) {
    int tid = threadIdx.x;
    if (tid < 512) g_hist[tid] = 0;
    if (tid == 0) {
        int odd_or = 0;
        #pragma unroll
        for (int i = 1; i < 128; i += 2) odd_or |= tg32[i];
        g_is64 = (odd_or == 0) ? 1 : 0;
    }
}

// ---------------------------------------------------------------------------
// Kernel 1: fp32 normalize -> bf16; targets -> int32; histogram.
// ---------------------------------------------------------------------------
__global__ __launch_bounds__(256) void normalize_k(const float* __restrict__ x,
                                                   const void* __restrict__ tg) {
    int row = blockIdx.x;
    int tid = threadIdx.x;
    float4 v = reinterpret_cast<const float4*>(x)[row * (ND / 4) + tid];
    float ss = v.x * v.x + v.y * v.y + v.z * v.z + v.w * v.w;
    #pragma unroll
    for (int o = 16; o; o >>= 1) ss += __shfl_xor_sync(0xffffffffu, ss, o);
    __shared__ float sh[8];
    if ((tid & 31) == 0) sh[tid >> 5] = ss;
    __syncthreads();
    if (tid < 32) {
        float t = (tid < 8) ? sh[tid] : 0.f;
        #pragma unroll
        for (int o = 4; o; o >>= 1) t += __shfl_xor_sync(0xffffffffu, t, o);
        if (tid == 0) sh[0] = t;
    }
    __syncthreads();
    float inv = 1.0f / fmaxf(sqrtf(sh[0]), 1e-12f);
    __nv_bfloat162 p0 = __floats2bfloat162_rn(v.x * inv, v.y * inv);
    __nv_bfloat162 p1 = __floats2bfloat162_rn(v.z * inv, v.w * inv);
    __nv_bfloat162* dst =
        reinterpret_cast<__nv_bfloat162*>(g_xb + (size_t)row * ND + tid * 4);
    dst[0] = p0; dst[1] = p1;
    if (tid == 0) {
        int t = g_is64 ? (int)((const long long*)tg)[row]
                       : ((const int*)tg)[row];
        g_tgt[row] = t;
        if ((unsigned)t < 512u) atomicAdd(&g_hist[t], 1);
    }
}

// ---------------------------------------------------------------------------
// Kernel 2: HMMA triangular GEMM + fused pos/neg LSE epilogue (all fp32).
// ---------------------------------------------------------------------------
__global__ __launch_bounds__(256) void gemm_k() {
    int bx = blockIdx.x, by = blockIdx.y;
    if (bx < by) return;
    const int rm = by * 128, cn = bx * 128;

    extern __shared__ char smem[];
    __shared__ int sh_tr[128], sh_tc[128];

    int tid = threadIdx.x, lane = tid & 31, wid = tid >> 5;
    int warp_m = wid >> 2, warp_n = wid & 3;

    if (tid < 128) sh_tr[tid] = g_tgt[rm + tid];
    else           sh_tc[tid - 128] = g_tgt[cn + tid - 128];

    const __nv_bfloat16* gA = g_xb + (size_t)rm * ND;
    const __nv_bfloat16* gB = g_xb + (size_t)cn * ND;
    uint32_t aSm = smem_u32(smem);                       // A stages: 3 * 10240
    uint32_t bSm = aSm + 3 * STAGE_BYTES;                // B stages: 3 * 10240

    int ch0 = tid * 2, ch1 = tid * 2 + 1;
    int cr0 = ch0 >> 2, cs0 = ch0 & 3, cr1 = ch1 >> 2, cs1 = ch1 & 3;
    uint32_t oA0 = (uint32_t)(cr0 * 80 + cs0 * 16), oA1 = (uint32_t)(cr1 * 80 + cs1 * 16);
    const __nv_bfloat16* pA0 = gA + (size_t)cr0 * ND + cs0 * 8;
    const __nv_bfloat16* pA1 = gA + (size_t)cr1 * ND + cs1 * 8;
    const __nv_bfloat16* pB0 = gB + (size_t)cr0 * ND + cs0 * 8;
    const __nv_bfloat16* pB1 = gB + (size_t)cr1 * ND + cs1 * 8;

    float acc[4][4][4];
    #pragma unroll
    for (int i = 0; i < 4; i++)
        #pragma unroll
        for (int j = 0; j < 4; j++)
            #pragma unroll
            for (int e = 0; e < 4; e++) acc[i][j][e] = 0.f;

    uint32_t aF = aSm + ((warp_m * 64 + (lane & 15)) * 40 + (lane >> 4) * 8) * 2;
    uint32_t bF = bSm + ((warp_n * 32 + ((lane & 15) & 7)) * 40 +
                         (((lane & 15) >> 3)) * 8) * 2;

    #pragma unroll
    for (int s = 0; s < 2; s++) {
        uint32_t so = s * STAGE_BYTES;
        cp16(aSm + so + oA0, pA0 + s * 32);
        cp16(aSm + so + oA1, pA1 + s * 32);
        cp16(bSm + so + oA0, pB0 + s * 32);
        cp16(bSm + so + oA1, pB1 + s * 32);
        CP_COMMIT();
    }

    int sc = 0;  // kc % 3
    for (int kc = 0; kc < 32; kc++) {
        if (kc < 30) { CP_WAIT(1); } else { CP_WAIT(0); }
        __syncthreads();
        if (kc + 2 < 32) {
            int sn = sc + 2; if (sn >= 3) sn -= 3;
            uint32_t so = (uint32_t)sn * STAGE_BYTES;
            cp16(aSm + so + oA0, pA0 + (kc + 2) * 32);
            cp16(aSm + so + oA1, pA1 + (kc + 2) * 32);
            cp16(bSm + so + oA0, pB0 + (kc + 2) * 32);
            cp16(bSm + so + oA1, pB1 + (kc + 2) * 32);
            CP_COMMIT();
        }
        uint32_t bo = (uint32_t)sc * STAGE_BYTES;
        #pragma unroll
        for (int kk = 0; kk < 2; kk++) {
            uint32_t af[4][4], bf2[4][2];
            #pragma unroll
            for (int am = 0; am < 4; am++)
                ldm_x4(aF + bo + am * 1280u + kk * 32u,
                       af[am][0], af[am][1], af[am][2], af[am][3]);
            #pragma unroll
            for (int an = 0; an < 4; an++)
                ldm_x2(bF + bo + an * 640u + kk * 32u, bf2[an][0], bf2[an][1]);
            #pragma unroll
            for (int am = 0; am < 4; am++)
                #pragma unroll
                for (int an = 0; an < 4; an++)
                    mma16816(acc[am][an], af[am], bf2[an]);
        }
        if (++sc == 3) sc = 0;
    }
    __syncthreads();   // all ldmatrix done before smem reuse below

    bool diag = (bx == by);
    int lr_base = warp_m * 64;
    int lc_base = warp_n * 32;

    // epilogue smem (floats, inside dynamic region):
    float* rowbufm  = reinterpret_cast<float*>(smem);          // [4][128]
    float* colbufm  = rowbufm + 512;                           // [2][128]
    float* mrow_sm  = colbufm + 256;                           // [128]
    float* mcol_sm  = mrow_sm + 128;                           // [128]
    float* rowbuf_n = mcol_sm + 128;                           // [4][128]
    float* colbuf_n = rowbuf_n + 512;                          // [2][128]
    float* rowbuf_p = colbuf_n + 256;                          // [4][128]
    float* colbuf_p = rowbuf_p + 512;                          // [2][128]

    // ---- P0: positive maxima per (row,tile) / (col,tile) — no exp --------
    {
        float rmax[4][2], cmax[4][2];
        #pragma unroll
        for (int a = 0; a < 4; a++) {
            rmax[a][0] = rmax[a][1] = NEG_INF;
            cmax[a][0] = cmax[a][1] = NEG_INF;
        }
        #pragma unroll
        for (int am = 0; am < 4; am++) {
            int r0 = lr_base + am * 16 + (lane >> 2);
            #pragma unroll
            for (int an = 0; an < 4; an++) {
                int c0 = lc_base + an * 8 + (lane & 3) * 2;
                #pragma unroll
                for (int e = 0; e < 4; e++) {
                    int rr = r0 + (e >> 1) * 8;
                    int cc = c0 + (e & 1);
                    if (sh_tr[rr] == sh_tc[cc] && !(diag && rr == cc)) {
                        float s = acc[am][an][e];
                        float lp = -fmaxf(1.25f - s, 0.f) * (s - 0.75f) * 64.f;
                        rmax[am][e >> 1] = fmaxf(rmax[am][e >> 1], lp);
                        cmax[an][e & 1]  = fmaxf(cmax[an][e & 1], lp);
                    }
                }
            }
        }
        #pragma unroll
        for (int am = 0; am < 4; am++)
            #pragma unroll
            for (int t = 0; t < 2; t++) {
                float v = rmax[am][t];
                v = fmaxf(v, __shfl_xor_sync(0xffffffffu, v, 1));
                v = fmaxf(v, __shfl_xor_sync(0xffffffffu, v, 2));
                if ((lane & 3) == 0)
                    rowbufm[warp_n * 128 + lr_base + am * 16 + t * 8 + (lane >> 2)] = v;
            }
        #pragma unroll
        for (int an = 0; an < 4; an++)
            #pragma unroll
            for (int c = 0; c < 2; c++) {
                float v = cmax[an][c];
                v = fmaxf(v, __shfl_xor_sync(0xffffffffu, v, 4));
                v = fmaxf(v, __shfl_xor_sync(0xffffffffu, v, 8));
                v = fmaxf(v, __shfl_xor_sync(0xffffffffu, v, 16));
                if (lane < 4)
                    colbufm[warp_m * 128 + lc_base + an * 8 + lane * 2 + c] = v;
            }
    }
    __syncthreads();
    if (tid < 128) {
        mrow_sm[tid] = fmaxf(fmaxf(rowbufm[tid], rowbufm[128 + tid]),
                             fmaxf(rowbufm[256 + tid], rowbufm[384 + tid]));
        mcol_sm[tid] = fmaxf(colbufm[tid], colbufm[128 + tid]);
    }
    __syncthreads();

    // ---- P1a: negative sums (fixed max 60) --------------------------------
    {
        float rsum[4][2], csum[4][2];
        #pragma unroll
        for (int a = 0; a < 4; a++) {
            rsum[a][0] = rsum[a][1] = 0.f;
            csum[a][0] = csum[a][1] = 0.f;
        }
        #pragma unroll
        for (int am = 0; am < 4; am++) {
            int r0 = lr_base + am * 16 + (lane >> 2);
            #pragma unroll
            for (int an = 0; an < 4; an++) {
                int c0 = lc_base + an * 8 + (lane & 3) * 2;
                #pragma unroll
                for (int e = 0; e < 4; e++) {
                    int rr = r0 + (e >> 1) * 8;
                    int cc = c0 + (e & 1);
                    float s = acc[am][an][e];
                    float ex = __expf(fmaxf(s + 0.25f, 0.f) * (s - 0.25f) * 64.f - 60.f);
                    if (sh_tr[rr] == sh_tc[cc]) ex = 0.f;
                    rsum[am][e >> 1] += ex;
                    csum[an][e & 1] += ex;
                }
            }
        }
        #pragma unroll
        for (int am = 0; am < 4; am++)
            #pragma unroll
            for (int t = 0; t < 2; t++) {
                float v = rsum[am][t];
                v += __shfl_xor_sync(0xffffffffu, v, 1);
                v += __shfl_xor_sync(0xffffffffu, v, 2);
                if ((lane & 3) == 0)
                    rowbuf_n[warp_n * 128 + lr_base + am * 16 + t * 8 + (lane >> 2)] = v;
            }
        #pragma unroll
        for (int an = 0; an < 4; an++)
            #pragma unroll
            for (int c = 0; c < 2; c++) {
                float v = csum[an][c];
                v += __shfl_xor_sync(0xffffffffu, v, 4);
                v += __shfl_xor_sync(0xffffffffu, v, 8);
                v += __shfl_xor_sync(0xffffffffu, v, 16);
                if (lane < 4)
                    colbuf_n[warp_m * 128 + lc_base + an * 8 + lane * 2 + c] = v;
            }
    }

    // ---- P1b: positive sums relative to exact maxima ----------------------
    {
        float rps[4][2], cps[4][2];
        #pragma unroll
        for (int a = 0; a < 4; a++) {
            rps[a][0] = rps[a][1] = 0.f;
            cps[a][0] = cps[a][1] = 0.f;
        }
        #pragma unroll
        for (int am = 0; am < 4; am++) {
            int r0 = lr_base + am * 16 + (lane >> 2);
            #pragma unroll
            for (int an = 0; an < 4; an++) {
                int c0 = lc_base + an * 8 + (lane & 3) * 2;
                #pragma unroll
                for (int e = 0; e < 4; e++) {
                    int rr = r0 + (e >> 1) * 8;
                    int cc = c0 + (e & 1);
                    if (sh_tr[rr] == sh_tc[cc] && !(diag && rr == cc)) {
                        float s = acc[am][an][e];
                        float lp = -fmaxf(1.25f - s, 0.f) * (s - 0.75f) * 64.f;
                        rps[am][e >> 1] += __expf(lp - mrow_sm[rr]);
                        cps[an][e & 1]  += __expf(lp - mcol_sm[cc]);
                    }
                }
            }
        }
        #pragma unroll
        for (int am = 0; am < 4; am++)
            #pragma unroll
            for (int t = 0; t < 2; t++) {
                float v = rps[am][t];
                v += __shfl_xor_sync(0xffffffffu, v, 1);
                v += __shfl_xor_sync(0xffffffffu, v, 2);
                if ((lane & 3) == 0)
                    rowbuf_p[warp_n * 128 + lr_base + am * 16 + t * 8 + (lane >> 2)] = v;
            }
        #pragma unroll
        for (int an = 0; an < 4; an++)
            #pragma unroll
            for (int c = 0; c < 2; c++) {
                float v = cps[an][c];
                v += __shfl_xor_sync(0xffffffffu, v, 4);
                v += __shfl_xor_sync(0xffffffffu, v, 8);
                v += __shfl_xor_sync(0xffffffffu, v, 16);
                if (lane < 4)
                    colbuf_p[warp_m * 128 + lc_base + an * 8 + lane * 2 + c] = v;
            }
    }
    __syncthreads();
    if (tid < 128) {
        float sn = rowbuf_n[tid] + rowbuf_n[128 + tid] +
                   rowbuf_n[256 + tid] + rowbuf_n[384 + tid];
        g_part_n[(size_t)(rm + tid) * NT + bx] = sn;
        float sp = rowbuf_p[tid] + rowbuf_p[128 + tid] +
                   rowbuf_p[256 + tid] + rowbuf_p[384 + tid];
        g_part_ps[(size_t)(rm + tid) * NT + bx] = sp;
        g_part_pm[(size_t)(rm + tid) * NT + bx] = mrow_sm[tid];
        if (bx > by) {
            g_part_n[(size_t)(cn + tid) * NT + by] = colbuf_n[tid] + colbuf_n[128 + tid];
            g_part_ps[(size_t)(cn + tid) * NT + by] = colbuf_p[tid] + colbuf_p[128 + tid];
            g_part_pm[(size_t)(cn + tid) * NT + by] = mcol_sm[tid];
        }
    }
}

// ---------------------------------------------------------------------------
// Kernel 3: per-row combine — one WARP per row. Neg: plain sum. Pos: online
// (m,s) merge of 64 pairs. Deterministic fixed order.
// ---------------------------------------------------------------------------
__global__ __launch_bounds__(256) void rowlse_k() {
    int row = blockIdx.x * 8 + (threadIdx.x >> 5);
    int lane = threadIdx.x & 31;

    float2 nv = reinterpret_cast<const float2*>(g_part_n + (size_t)row * NT)[lane];
    float sn = nv.x + nv.y;
    #pragma unroll
    for (int o = 16; o; o >>= 1) sn += __shfl_xor_sync(0xffffffffu, sn, o);

    float2 mv = reinterpret_cast<const float2*>(g_part_pm + (size_t)row * NT)[lane];
    float2 sv = reinterpret_cast<const float2*>(g_part_ps + (size_t)row * NT)[lane];
    float m = fmaxf(mv.x, mv.y);
    float s = sv.x * __expf(mv.x - m) + sv.y * __expf(mv.y - m);
    #pragma unroll
    for (int o = 16; o; o >>= 1) {
        float mo = __shfl_xor_sync(0xffffffffu, m, o);
        float so = __shfl_xor_sync(0xffffffffu, s, o);
        float mm = fmaxf(m, mo);
        s = s * __expf(m - mm) + so * __expf(mo - mm);
        m = mm;
    }

    if (lane == 0) {
        int t = g_tgt[row];
        int c = ((unsigned)t < 512u) ? g_hist[t] : 0;
        int valid = (c >= 2) && (c < NB);
        float loss = 0.f;
        if (valid) {
            sn = fmaxf(sn, 1e-37f);
            s = fmaxf(s, 1e-37f);
            float x = 60.f + logf(sn) + m + logf(s);
            loss = fmaxf(x, 0.f) + log1pf(expf(-fabsf(x)));
        }
        g_loss[row] = loss;
    }
}

// ---------------------------------------------------------------------------
// Kernel 4: deterministic final reduction (validity from histogram).
// ---------------------------------------------------------------------------
__global__ __launch_bounds__(1024) void finalize_k(float* __restrict__ out) {
    __shared__ float sh_s[1024];
    __shared__ int sh_c[1024];
    int tid = threadIdx.x;
    float t = 0.f;
    int c = 0;
    for (int r = tid; r < NB; r += 1024) {
        t += g_loss[r];
        int tv = g_tgt[r];
        int cnt = ((unsigned)tv < 512u) ? g_hist[tv] : 0;
        c += ((cnt >= 2) && (cnt < NB)) ? 1 : 0;
    }
    sh_s[tid] = t; sh_c[tid] = c;
    __syncthreads();
    for (int off = 512; off > 0; off >>= 1) {
        if (tid < off) {
            sh_s[tid] += sh_s[tid + off];
            sh_c[tid] += sh_c[tid + off];
        }
        __syncthreads();
    }
    if (tid == 0) {
        int cnt = sh_c[0] > 1 ? sh_c[0] : 1;
        out[0] = sh_s[0] / (float)cnt;
    }
}

// ---------------------------------------------------------------------------
extern "C" void kernel_launch(void* const* d_in, const int* in_sizes, int n_in,
                              void* d_out, int out_size) {
    const float* x = (const float*)d_in[0];
    const void* tg = d_in[1];
    float* out = (float*)d_out;

    cudaFuncSetAttribute(gemm_k, cudaFuncAttributeMaxDynamicSharedMemorySize, 61440);

    detect_k<<<1, 512>>>((const int*)tg);
    normalize_k<<<NB, 256>>>(x, tg);
    gemm_k<<<dim3(NT, NT), 256, 61440>>>();
    rowlse_k<<<NB / 8, 256>>>();
    finalize_k<<<1, 1024>>>(out);
}

// round 12
// speedup vs baseline: 1.3456x; 1.0459x over previous
#include <cuda_runtime.h>
#include <cuda_bf16.h>
#include <math.h>
#include <stdint.h>

// ---------------------------------------------------------------------------
// CircleLoss forward, B=8192, D=1024, N_IDS=512 — mma.sync bf16 edition, v6.
//  1) normalize (fp32) -> bf16 g_xb; target histogram
//  2) triangular 128x128-tile HMMA GEMM (2-D grid, early exit), 3-stage
//     cp.async pipeline, __launch_bounds__(256,2) for 2 CTAs/SM overlap.
//     Fused fp32 epilogue: P0 exact pos maxima; P1 single pass computing
//     neg exp(l-60) sums and pos exp(lp-m) sums together.
//  3) rowlse (warp per row): online (m,s) merge + neg sums -> softplus.
//  4) deterministic mean.
// ---------------------------------------------------------------------------

#define NB 8192
#define ND 1024
#define NT 64               // 8192 / 128 tiles
#define STAGE_BYTES 10240u  // 128 rows * 80 B (40 halves, padded)
#define NEG_INF (-1e30f)

__device__ __nv_bfloat16 g_xb[NB * ND];     // 16 MB (L2-resident)
__device__ float g_part_n[NB * NT];         // 2 MB  neg exp-sums
__device__ float g_part_pm[NB * NT];        // 2 MB  pos max per (row,tile)
__device__ float g_part_ps[NB * NT];        // 2 MB  pos exp-sum rel. to max
__device__ float g_loss[NB];
__device__ int   g_tgt[NB];
__device__ int   g_hist[512];
__device__ int   g_is64;

// ---------------- PTX helpers ----------------------------------------------
__device__ __forceinline__ uint32_t smem_u32(const void* p) {
    uint32_t a;
    asm("{ .reg .u64 t; cvta.to.shared.u64 t, %1; cvt.u32.u64 %0, t; }"
        : "=r"(a) : "l"(p));
    return a;
}
__device__ __forceinline__ void cp16(uint32_t dst, const void* src) {
    asm volatile("cp.async.cg.shared.global [%0], [%1], 16;"
                 :: "r"(dst), "l"(src) : "memory");
}
#define CP_COMMIT() asm volatile("cp.async.commit_group;" ::: "memory")
#define CP_WAIT(n)  asm volatile("cp.async.wait_group %0;" :: "n"(n) : "memory")

__device__ __forceinline__ void ldm_x4(uint32_t a, uint32_t& r0, uint32_t& r1,
                                       uint32_t& r2, uint32_t& r3) {
    asm volatile("ldmatrix.sync.aligned.m8n8.x4.shared.b16 {%0,%1,%2,%3}, [%4];"
                 : "=r"(r0), "=r"(r1), "=r"(r2), "=r"(r3) : "r"(a));
}
__device__ __forceinline__ void ldm_x2(uint32_t a, uint32_t& r0, uint32_t& r1) {
    asm volatile("ldmatrix.sync.aligned.m8n8.x2.shared.b16 {%0,%1}, [%2];"
                 : "=r"(r0), "=r"(r1) : "r"(a));
}
__device__ __forceinline__ void mma16816(float* d, const uint32_t* a,
                                         const uint32_t* b) {
    asm volatile(
        "mma.sync.aligned.m16n8k16.row.col.f32.bf16.bf16.f32 "
        "{%0,%1,%2,%3}, {%4,%5,%6,%7}, {%8,%9}, {%0,%1,%2,%3};"
        : "+f"(d[0]), "+f"(d[1]), "+f"(d[2]), "+f"(d[3])
        : "r"(a[0]), "r"(a[1]), "r"(a[2]), "r"(a[3]), "r"(b[0]), "r"(b[1]));
}

// ---------------------------------------------------------------------------
// Kernel 0: zero histogram; detect targets dtype (int64 LE has odd words 0).
// ---------------------------------------------------------------------------
__global__ void detect_k(const int* __restrict__ tg32) {
    int tid = threadIdx.x;
    if (tid < 512) g_hist[tid] = 0;
    if (tid == 0) {
        int odd_or = 0;
        #pragma unroll
        for (int i = 1; i < 128; i += 2) odd_or |= tg32[i];
        g_is64 = (odd_or == 0) ? 1 : 0;
    }
}

// ---------------------------------------------------------------------------
// Kernel 1: fp32 normalize -> bf16; targets -> int32; histogram.
// ---------------------------------------------------------------------------
__global__ __launch_bounds__(256) void normalize_k(const float* __restrict__ x,
                                                   const void* __restrict__ tg) {
    int row = blockIdx.x;
    int tid = threadIdx.x;
    float4 v = reinterpret_cast<const float4*>(x)[row * (ND / 4) + tid];
    float ss = v.x * v.x + v.y * v.y + v.z * v.z + v.w * v.w;
    #pragma unroll
    for (int o = 16; o; o >>= 1) ss += __shfl_xor_sync(0xffffffffu, ss, o);
    __shared__ float sh[8];
    if ((tid & 31) == 0) sh[tid >> 5] = ss;
    __syncthreads();
    if (tid < 32) {
        float t = (tid < 8) ? sh[tid] : 0.f;
        #pragma unroll
        for (int o = 4; o; o >>= 1) t += __shfl_xor_sync(0xffffffffu, t, o);
        if (tid == 0) sh[0] = t;
    }
    __syncthreads();
    float inv = 1.0f / fmaxf(sqrtf(sh[0]), 1e-12f);
    __nv_bfloat162 p0 = __floats2bfloat162_rn(v.x * inv, v.y * inv);
    __nv_bfloat162 p1 = __floats2bfloat162_rn(v.z * inv, v.w * inv);
    __nv_bfloat162* dst =
        reinterpret_cast<__nv_bfloat162*>(g_xb + (size_t)row * ND + tid * 4);
    dst[0] = p0; dst[1] = p1;
    if (tid == 0) {
        int t = g_is64 ? (int)((const long long*)tg)[row]
                       : ((const int*)tg)[row];
        g_tgt[row] = t;
        if ((unsigned)t < 512u) atomicAdd(&g_hist[t], 1);
    }
}

// ---------------------------------------------------------------------------
// Kernel 2: HMMA triangular GEMM + fused pos/neg LSE epilogue (all fp32).
// 2 CTAs/SM target via launch bounds; fused single-sweep epilogue.
// ---------------------------------------------------------------------------
__global__ __launch_bounds__(256, 2) void gemm_k() {
    int bx = blockIdx.x, by = blockIdx.y;
    if (bx < by) return;
    const int rm = by * 128, cn = bx * 128;

    extern __shared__ char smem[];
    __shared__ int sh_tr[128], sh_tc[128];

    int tid = threadIdx.x, lane = tid & 31, wid = tid >> 5;
    int warp_m = wid >> 2, warp_n = wid & 3;

    if (tid < 128) sh_tr[tid] = g_tgt[rm + tid];
    else           sh_tc[tid - 128] = g_tgt[cn + tid - 128];

    const __nv_bfloat16* gA = g_xb + (size_t)rm * ND;
    const __nv_bfloat16* gB = g_xb + (size_t)cn * ND;
    uint32_t aSm = smem_u32(smem);                       // A stages: 3 * 10240
    uint32_t bSm = aSm + 3 * STAGE_BYTES;                // B stages: 3 * 10240

    int ch0 = tid * 2, ch1 = tid * 2 + 1;
    int cr0 = ch0 >> 2, cs0 = ch0 & 3, cr1 = ch1 >> 2, cs1 = ch1 & 3;
    uint32_t oA0 = (uint32_t)(cr0 * 80 + cs0 * 16), oA1 = (uint32_t)(cr1 * 80 + cs1 * 16);
    const __nv_bfloat16* pA0 = gA + (size_t)cr0 * ND + cs0 * 8;
    const __nv_bfloat16* pA1 = gA + (size_t)cr1 * ND + cs1 * 8;
    const __nv_bfloat16* pB0 = gB + (size_t)cr0 * ND + cs0 * 8;
    const __nv_bfloat16* pB1 = gB + (size_t)cr1 * ND + cs1 * 8;

    float acc[4][4][4];
    #pragma unroll
    for (int i = 0; i < 4; i++)
        #pragma unroll
        for (int j = 0; j < 4; j++)
            #pragma unroll
            for (int e = 0; e < 4; e++) acc[i][j][e] = 0.f;

    uint32_t aF = aSm + ((warp_m * 64 + (lane & 15)) * 40 + (lane >> 4) * 8) * 2;
    uint32_t bF = bSm + ((warp_n * 32 + ((lane & 15) & 7)) * 40 +
                         (((lane & 15) >> 3)) * 8) * 2;

    #pragma unroll
    for (int s = 0; s < 2; s++) {
        uint32_t so = s * STAGE_BYTES;
        cp16(aSm + so + oA0, pA0 + s * 32);
        cp16(aSm + so + oA1, pA1 + s * 32);
        cp16(bSm + so + oA0, pB0 + s * 32);
        cp16(bSm + so + oA1, pB1 + s * 32);
        CP_COMMIT();
    }

    int sc = 0;  // kc % 3
    for (int kc = 0; kc < 32; kc++) {
        if (kc < 30) { CP_WAIT(1); } else { CP_WAIT(0); }
        __syncthreads();
        if (kc + 2 < 32) {
            int sn = sc + 2; if (sn >= 3) sn -= 3;
            uint32_t so = (uint32_t)sn * STAGE_BYTES;
            cp16(aSm + so + oA0, pA0 + (kc + 2) * 32);
            cp16(aSm + so + oA1, pA1 + (kc + 2) * 32);
            cp16(bSm + so + oA0, pB0 + (kc + 2) * 32);
            cp16(bSm + so + oA1, pB1 + (kc + 2) * 32);
            CP_COMMIT();
        }
        uint32_t bo = (uint32_t)sc * STAGE_BYTES;
        #pragma unroll
        for (int kk = 0; kk < 2; kk++) {
            uint32_t af[4][4], bf2[4][2];
            #pragma unroll
            for (int am = 0; am < 4; am++)
                ldm_x4(aF + bo + am * 1280u + kk * 32u,
                       af[am][0], af[am][1], af[am][2], af[am][3]);
            #pragma unroll
            for (int an = 0; an < 4; an++)
                ldm_x2(bF + bo + an * 640u + kk * 32u, bf2[an][0], bf2[an][1]);
            #pragma unroll
            for (int am = 0; am < 4; am++)
                #pragma unroll
                for (int an = 0; an < 4; an++)
                    mma16816(acc[am][an], af[am], bf2[an]);
        }
        if (++sc == 3) sc = 0;
    }
    __syncthreads();   // all ldmatrix done before smem reuse below

    bool diag = (bx == by);
    int lr_base = warp_m * 64;
    int lc_base = warp_n * 32;

    // epilogue smem (floats, inside dynamic region):
    float* rowbufm  = reinterpret_cast<float*>(smem);          // [4][128]
    float* colbufm  = rowbufm + 512;                           // [2][128]
    float* mrow_sm  = colbufm + 256;                           // [128]
    float* mcol_sm  = mrow_sm + 128;                           // [128]
    float* rowbuf_n = mcol_sm + 128;                           // [4][128]
    float* colbuf_n = rowbuf_n + 512;                          // [2][128]
    float* rowbuf_p = colbuf_n + 256;                          // [4][128]
    float* colbuf_p = rowbuf_p + 512;                          // [2][128]

    // ---- P0: positive maxima per (row,tile) / (col,tile) — no exp --------
    {
        float rmax[4][2], cmax[4][2];
        #pragma unroll
        for (int a = 0; a < 4; a++) {
            rmax[a][0] = rmax[a][1] = NEG_INF;
            cmax[a][0] = cmax[a][1] = NEG_INF;
        }
        #pragma unroll
        for (int am = 0; am < 4; am++) {
            int r0 = lr_base + am * 16 + (lane >> 2);
            #pragma unroll
            for (int an = 0; an < 4; an++) {
                int c0 = lc_base + an * 8 + (lane & 3) * 2;
                #pragma unroll
                for (int e = 0; e < 4; e++) {
                    int rr = r0 + (e >> 1) * 8;
                    int cc = c0 + (e & 1);
                    if (sh_tr[rr] == sh_tc[cc] && !(diag && rr == cc)) {
                        float s = acc[am][an][e];
                        float lp = -fmaxf(1.25f - s, 0.f) * (s - 0.75f) * 64.f;
                        rmax[am][e >> 1] = fmaxf(rmax[am][e >> 1], lp);
                        cmax[an][e & 1]  = fmaxf(cmax[an][e & 1], lp);
                    }
                }
            }
        }
        #pragma unroll
        for (int am = 0; am < 4; am++)
            #pragma unroll
            for (int t = 0; t < 2; t++) {
                float v = rmax[am][t];
                v = fmaxf(v, __shfl_xor_sync(0xffffffffu, v, 1));
                v = fmaxf(v, __shfl_xor_sync(0xffffffffu, v, 2));
                if ((lane & 3) == 0)
                    rowbufm[warp_n * 128 + lr_base + am * 16 + t * 8 + (lane >> 2)] = v;
            }
        #pragma unroll
        for (int an = 0; an < 4; an++)
            #pragma unroll
            for (int c = 0; c < 2; c++) {
                float v = cmax[an][c];
                v = fmaxf(v, __shfl_xor_sync(0xffffffffu, v, 4));
                v = fmaxf(v, __shfl_xor_sync(0xffffffffu, v, 8));
                v = fmaxf(v, __shfl_xor_sync(0xffffffffu, v, 16));
                if (lane < 4)
                    colbufm[warp_m * 128 + lc_base + an * 8 + lane * 2 + c] = v;
            }
    }
    __syncthreads();
    if (tid < 128) {
        mrow_sm[tid] = fmaxf(fmaxf(rowbufm[tid], rowbufm[128 + tid]),
                             fmaxf(rowbufm[256 + tid], rowbufm[384 + tid]));
        mcol_sm[tid] = fmaxf(colbufm[tid], colbufm[128 + tid]);
    }
    __syncthreads();

    // ---- P1: fused single sweep — neg sums (fixed max 60) + pos sums ------
    {
        float rsum[4][2], csum[4][2], rps[4][2], cps[4][2];
        #pragma unroll
        for (int a = 0; a < 4; a++) {
            rsum[a][0] = rsum[a][1] = 0.f;
            csum[a][0] = csum[a][1] = 0.f;
            rps[a][0] = rps[a][1] = 0.f;
            cps[a][0] = cps[a][1] = 0.f;
        }
        #pragma unroll
        for (int am = 0; am < 4; am++) {
            int r0 = lr_base + am * 16 + (lane >> 2);
            #pragma unroll
            for (int an = 0; an < 4; an++) {
                int c0 = lc_base + an * 8 + (lane & 3) * 2;
                #pragma unroll
                for (int e = 0; e < 4; e++) {
                    int rr = r0 + (e >> 1) * 8;
                    int cc = c0 + (e & 1);
                    float s = acc[am][an][e];
                    bool same = (sh_tr[rr] == sh_tc[cc]);
                    if (!same) {
                        float ex = __expf(fmaxf(s + 0.25f, 0.f) * (s - 0.25f) * 64.f - 60.f);
                        rsum[am][e >> 1] += ex;
                        csum[an][e & 1] += ex;
                    } else if (!(diag && rr == cc)) {
                        float lp = -fmaxf(1.25f - s, 0.f) * (s - 0.75f) * 64.f;
                        rps[am][e >> 1] += __expf(lp - mrow_sm[rr]);
                        cps[an][e & 1]  += __expf(lp - mcol_sm[cc]);
                    }
                }
            }
        }
        #pragma unroll
        for (int am = 0; am < 4; am++)
            #pragma unroll
            for (int t = 0; t < 2; t++) {
                float v = rsum[am][t];
                v += __shfl_xor_sync(0xffffffffu, v, 1);
                v += __shfl_xor_sync(0xffffffffu, v, 2);
                float w = rps[am][t];
                w += __shfl_xor_sync(0xffffffffu, w, 1);
                w += __shfl_xor_sync(0xffffffffu, w, 2);
                if ((lane & 3) == 0) {
                    int idx = warp_n * 128 + lr_base + am * 16 + t * 8 + (lane >> 2);
                    rowbuf_n[idx] = v;
                    rowbuf_p[idx] = w;
                }
            }
        #pragma unroll
        for (int an = 0; an < 4; an++)
            #pragma unroll
            for (int c = 0; c < 2; c++) {
                float v = csum[an][c];
                v += __shfl_xor_sync(0xffffffffu, v, 4);
                v += __shfl_xor_sync(0xffffffffu, v, 8);
                v += __shfl_xor_sync(0xffffffffu, v, 16);
                float w = cps[an][c];
                w += __shfl_xor_sync(0xffffffffu, w, 4);
                w += __shfl_xor_sync(0xffffffffu, w, 8);
                w += __shfl_xor_sync(0xffffffffu, w, 16);
                if (lane < 4) {
                    int idx = warp_m * 128 + lc_base + an * 8 + lane * 2 + c;
                    colbuf_n[idx] = v;
                    colbuf_p[idx] = w;
                }
            }
    }
    __syncthreads();
    if (tid < 128) {
        float sn = rowbuf_n[tid] + rowbuf_n[128 + tid] +
                   rowbuf_n[256 + tid] + rowbuf_n[384 + tid];
        g_part_n[(size_t)(rm + tid) * NT + bx] = sn;
        float sp = rowbuf_p[tid] + rowbuf_p[128 + tid] +
                   rowbuf_p[256 + tid] + rowbuf_p[384 + tid];
        g_part_ps[(size_t)(rm + tid) * NT + bx] = sp;
        g_part_pm[(size_t)(rm + tid) * NT + bx] = mrow_sm[tid];
        if (bx > by) {
            g_part_n[(size_t)(cn + tid) * NT + by] = colbuf_n[tid] + colbuf_n[128 + tid];
            g_part_ps[(size_t)(cn + tid) * NT + by] = colbuf_p[tid] + colbuf_p[128 + tid];
            g_part_pm[(size_t)(cn + tid) * NT + by] = mcol_sm[tid];
        }
    }
}

// ---------------------------------------------------------------------------
// Kernel 3: per-row combine — one WARP per row. Neg: plain sum. Pos: online
// (m,s) merge of 64 pairs. Deterministic fixed order.
// ---------------------------------------------------------------------------
__global__ __launch_bounds__(256) void rowlse_k() {
    int row = blockIdx.x * 8 + (threadIdx.x >> 5);
    int lane = threadIdx.x & 31;

    float2 nv = reinterpret_cast<const float2*>(g_part_n + (size_t)row * NT)[lane];
    float sn = nv.x + nv.y;
    #pragma unroll
    for (int o = 16; o; o >>= 1) sn += __shfl_xor_sync(0xffffffffu, sn, o);

    float2 mv = reinterpret_cast<const float2*>(g_part_pm + (size_t)row * NT)[lane];
    float2 sv = reinterpret_cast<const float2*>(g_part_ps + (size_t)row * NT)[lane];
    float m = fmaxf(mv.x, mv.y);
    float s = sv.x * __expf(mv.x - m) + sv.y * __expf(mv.y - m);
    #pragma unroll
    for (int o = 16; o; o >>= 1) {
        float mo = __shfl_xor_sync(0xffffffffu, m, o);
        float so = __shfl_xor_sync(0xffffffffu, s, o);
        float mm = fmaxf(m, mo);
        s = s * __expf(m - mm) + so * __expf(mo - mm);
        m = mm;
    }

    if (lane == 0) {
        int t = g_tgt[row];
        int c = ((unsigned)t < 512u) ? g_hist[t] : 0;
        int valid = (c >= 2) && (c < NB);
        float loss = 0.f;
        if (valid) {
            sn = fmaxf(sn, 1e-37f);
            s = fmaxf(s, 1e-37f);
            float x = 60.f + logf(sn) + m + logf(s);
            loss = fmaxf(x, 0.f) + log1pf(expf(-fabsf(x)));
        }
        g_loss[row] = loss;
    }
}

// ---------------------------------------------------------------------------
// Kernel 4: deterministic final reduction (validity from histogram).
// ---------------------------------------------------------------------------
__global__ __launch_bounds__(1024) void finalize_k(float* __restrict__ out) {
    __shared__ float sh_s[1024];
    __shared__ int sh_c[1024];
    int tid = threadIdx.x;
    float t = 0.f;
    int c = 0;
    for (int r = tid; r < NB; r += 1024) {
        t += g_loss[r];
        int tv = g_tgt[r];
        int cnt = ((unsigned)tv < 512u) ? g_hist[tv] : 0;
        c += ((cnt >= 2) && (cnt < NB)) ? 1 : 0;
    }
    sh_s[tid] = t; sh_c[tid] = c;
    __syncthreads();
    for (int off = 512; off > 0; off >>= 1) {
        if (tid < off) {
            sh_s[tid] += sh_s[tid + off];
            sh_c[tid] += sh_c[tid + off];
        }
        __syncthreads();
    }
    if (tid == 0) {
        int cnt = sh_c[0] > 1 ? sh_c[0] : 1;
        out[0] = sh_s[0] / (float)cnt;
    }
}

// ---------------------------------------------------------------------------
extern "C" void kernel_launch(void* const* d_in, const int* in_sizes, int n_in,
                              void* d_out, int out_size) {
    const float* x = (const float*)d_in[0];
    const void* tg = d_in[1];
    float* out = (float*)d_out;

    cudaFuncSetAttribute(gemm_k, cudaFuncAttributeMaxDynamicSharedMemorySize, 61440);

    detect_k<<<1, 512>>>((const int*)tg);
    normalize_k<<<NB, 256>>>(x, tg);
    gemm_k<<<dim3(NT, NT), 256, 61440>>>();
    rowlse_k<<<NB / 8, 256>>>();
    finalize_k<<<1, 1024>>>(out);
}

// round 14
// speedup vs baseline: 1.6535x; 1.2288x over previous
#include <cuda_runtime.h>
#include <cuda_bf16.h>
#include <math.h>
#include <stdint.h>

// ---------------------------------------------------------------------------
// CircleLoss forward, B=8192, D=1024, N_IDS=512 — mma.sync bf16 edition, v7.
//  1) normalize (fp32) -> bf16 g_xb; target histogram
//  2) triangular 128x128-tile HMMA GEMM (2-D grid, early exit), BK=64,
//     3-stage cp.async pipeline (one barrier per 64-MMA iteration),
//     __launch_bounds__(256,2). Fused fp32 epilogue: P0 exact pos maxima;
//     P1 single sweep of neg exp(l-60) sums + pos exp(lp-m) sums.
//  3) rowlse (warp per row): online (m,s) merge + neg sums -> softplus.
//  4) deterministic mean.
// ---------------------------------------------------------------------------

#define NB 8192
#define ND 1024
#define NT 64               // 8192 / 128 tiles
#define ROWB 144u           // bytes per smem row (72 halves, conflict-free)
#define STAGE_BYTES 18432u  // 128 rows * 144 B
#define NEG_INF (-1e30f)

__device__ __nv_bfloat16 g_xb[NB * ND];     // 16 MB (L2-resident)
__device__ float g_part_n[NB * NT];         // 2 MB  neg exp-sums
__device__ float g_part_pm[NB * NT];        // 2 MB  pos max per (row,tile)
__device__ float g_part_ps[NB * NT];        // 2 MB  pos exp-sum rel. to max
__device__ float g_loss[NB];
__device__ int   g_tgt[NB];
__device__ int   g_hist[512];
__device__ int   g_is64;

// ---------------- PTX helpers ----------------------------------------------
__device__ __forceinline__ uint32_t smem_u32(const void* p) {
    uint32_t a;
    asm("{ .reg .u64 t; cvta.to.shared.u64 t, %1; cvt.u32.u64 %0, t; }"
        : "=r"(a) : "l"(p));
    return a;
}
__device__ __forceinline__ void cp16(uint32_t dst, const void* src) {
    asm volatile("cp.async.cg.shared.global [%0], [%1], 16;"
                 :: "r"(dst), "l"(src) : "memory");
}
#define CP_COMMIT() asm volatile("cp.async.commit_group;" ::: "memory")
#define CP_WAIT(n)  asm volatile("cp.async.wait_group %0;" :: "n"(n) : "memory")

__device__ __forceinline__ void ldm_x4(uint32_t a, uint32_t& r0, uint32_t& r1,
                                       uint32_t& r2, uint32_t& r3) {
    asm volatile("ldmatrix.sync.aligned.m8n8.x4.shared.b16 {%0,%1,%2,%3}, [%4];"
                 : "=r"(r0), "=r"(r1), "=r"(r2), "=r"(r3) : "r"(a));
}
__device__ __forceinline__ void ldm_x2(uint32_t a, uint32_t& r0, uint32_t& r1) {
    asm volatile("ldmatrix.sync.aligned.m8n8.x2.shared.b16 {%0,%1}, [%2];"
                 : "=r"(r0), "=r"(r1) : "r"(a));
}
__device__ __forceinline__ void mma16816(float* d, const uint32_t* a,
                                         const uint32_t* b) {
    asm volatile(
        "mma.sync.aligned.m16n8k16.row.col.f32.bf16.bf16.f32 "
        "{%0,%1,%2,%3}, {%4,%5,%6,%7}, {%8,%9}, {%0,%1,%2,%3};"
        : "+f"(d[0]), "+f"(d[1]), "+f"(d[2]), "+f"(d[3])
        : "r"(a[0]), "r"(a[1]), "r"(a[2]), "r"(a[3]), "r"(b[0]), "r"(b[1]));
}

// ---------------------------------------------------------------------------
// Kernel 0: zero histogram; detect targets dtype (int64 LE has odd words 0).
// ---------------------------------------------------------------------------
__global__ void detect_k(const int* __restrict__ tg32) {
    int tid = threadIdx.x;
    if (tid < 512) g_hist[tid] = 0;
    if (tid == 0) {
        int odd_or = 0;
        #pragma unroll
        for (int i = 1; i < 128; i += 2) odd_or |= tg32[i];
        g_is64 = (odd_or == 0) ? 1 : 0;
    }
}

// ---------------------------------------------------------------------------
// Kernel 1: fp32 normalize -> bf16; targets -> int32; histogram.
// ---------------------------------------------------------------------------
__global__ __launch_bounds__(256) void normalize_k(const float* __restrict__ x,
                                                   const void* __restrict__ tg) {
    int row = blockIdx.x;
    int tid = threadIdx.x;
    float4 v = reinterpret_cast<const float4*>(x)[row * (ND / 4) + tid];
    float ss = v.x * v.x + v.y * v.y + v.z * v.z + v.w * v.w;
    #pragma unroll
    for (int o = 16; o; o >>= 1) ss += __shfl_xor_sync(0xffffffffu, ss, o);
    __shared__ float sh[8];
    if ((tid & 31) == 0) sh[tid >> 5] = ss;
    __syncthreads();
    if (tid < 32) {
        float t = (tid < 8) ? sh[tid] : 0.f;
        #pragma unroll
        for (int o = 4; o; o >>= 1) t += __shfl_xor_sync(0xffffffffu, t, o);
        if (tid == 0) sh[0] = t;
    }
    __syncthreads();
    float inv = 1.0f / fmaxf(sqrtf(sh[0]), 1e-12f);
    __nv_bfloat162 p0 = __floats2bfloat162_rn(v.x * inv, v.y * inv);
    __nv_bfloat162 p1 = __floats2bfloat162_rn(v.z * inv, v.w * inv);
    __nv_bfloat162* dst =
        reinterpret_cast<__nv_bfloat162*>(g_xb + (size_t)row * ND + tid * 4);
    dst[0] = p0; dst[1] = p1;
    if (tid == 0) {
        int t = g_is64 ? (int)((const long long*)tg)[row]
                       : ((const int*)tg)[row];
        g_tgt[row] = t;
        if ((unsigned)t < 512u) atomicAdd(&g_hist[t], 1);
    }
}

// ---------------------------------------------------------------------------
// Kernel 2: HMMA triangular GEMM + fused pos/neg LSE epilogue (all fp32).
// BK=64, 3-stage, 16 iterations, one barrier per iteration, 2 CTAs/SM.
// ---------------------------------------------------------------------------
__global__ __launch_bounds__(256, 2) void gemm_k() {
    int bx = blockIdx.x, by = blockIdx.y;
    if (bx < by) return;
    const int rm = by * 128, cn = bx * 128;

    extern __shared__ char smem[];
    __shared__ int sh_tr[128], sh_tc[128];

    int tid = threadIdx.x, lane = tid & 31, wid = tid >> 5;
    int warp_m = wid >> 2, warp_n = wid & 3;

    if (tid < 128) sh_tr[tid] = g_tgt[rm + tid];
    else           sh_tc[tid - 128] = g_tgt[cn + tid - 128];

    const __nv_bfloat16* gA = g_xb + (size_t)rm * ND;
    const __nv_bfloat16* gB = g_xb + (size_t)cn * ND;
    uint32_t aSm = smem_u32(smem);                       // A stages: 3 * 18432
    uint32_t bSm = aSm + 3 * STAGE_BYTES;                // B stages: 3 * 18432

    // copy lanes: 1024 16B-chunks per tile (128 rows x 8), 4 per thread
    int ch[4]; uint32_t off[4];
    #pragma unroll
    for (int q = 0; q < 4; q++) {
        ch[q] = q * 256 + tid;
        int r = ch[q] >> 3, c16 = ch[q] & 7;
        off[q] = (uint32_t)r * ROWB + (uint32_t)c16 * 16u;
    }

    float acc[4][4][4];
    #pragma unroll
    for (int i = 0; i < 4; i++)
        #pragma unroll
        for (int j = 0; j < 4; j++)
            #pragma unroll
            for (int e = 0; e < 4; e++) acc[i][j][e] = 0.f;

    // ldmatrix base addrs (row pitch 72 halves = 144 B)
    uint32_t aF = aSm + (uint32_t)(warp_m * 64 + (lane & 15)) * ROWB + (uint32_t)(lane >> 4) * 16u;
    uint32_t bF = bSm + (uint32_t)(warp_n * 32 + ((lane & 15) & 7)) * ROWB +
                  (uint32_t)((lane & 15) >> 3) * 16u;

    // prefetch stages 0, 1
    #pragma unroll
    for (int s = 0; s < 2; s++) {
        uint32_t so = s * STAGE_BYTES;
        #pragma unroll
        for (int q = 0; q < 4; q++) {
            int r = ch[q] >> 3, c16 = ch[q] & 7;
            cp16(aSm + so + off[q], gA + (size_t)r * ND + s * 64 + c16 * 8);
            cp16(bSm + so + off[q], gB + (size_t)r * ND + s * 64 + c16 * 8);
        }
        CP_COMMIT();
    }

    int sc = 0;  // kc % 3
    for (int kc = 0; kc < 16; kc++) {
        if (kc < 14) { CP_WAIT(1); } else { CP_WAIT(0); }
        __syncthreads();
        if (kc + 2 < 16) {
            int sn = sc + 2; if (sn >= 3) sn -= 3;
            uint32_t so = (uint32_t)sn * STAGE_BYTES;
            #pragma unroll
            for (int q = 0; q < 4; q++) {
                int r = ch[q] >> 3, c16 = ch[q] & 7;
                cp16(aSm + so + off[q], gA + (size_t)r * ND + (kc + 2) * 64 + c16 * 8);
                cp16(bSm + so + off[q], gB + (size_t)r * ND + (kc + 2) * 64 + c16 * 8);
            }
            CP_COMMIT();
        }
        uint32_t bo = (uint32_t)sc * STAGE_BYTES;
        #pragma unroll
        for (int kk = 0; kk < 4; kk++) {
            uint32_t af[4][4], bf2[4][2];
            #pragma unroll
            for (int am = 0; am < 4; am++)
                ldm_x4(aF + bo + (uint32_t)am * (16u * ROWB) + (uint32_t)kk * 32u,
                       af[am][0], af[am][1], af[am][2], af[am][3]);
            #pragma unroll
            for (int an = 0; an < 4; an++)
                ldm_x2(bF + bo + (uint32_t)an * (8u * ROWB) + (uint32_t)kk * 32u,
                       bf2[an][0], bf2[an][1]);
            #pragma unroll
            for (int am = 0; am < 4; am++)
                #pragma unroll
                for (int an = 0; an < 4; an++)
                    mma16816(acc[am][an], af[am], bf2[an]);
        }
        if (++sc == 3) sc = 0;
    }
    __syncthreads();   // all ldmatrix done before smem reuse below

    bool diag = (bx == by);
    int lr_base = warp_m * 64;
    int lc_base = warp_n * 32;

    // epilogue smem (floats, inside dynamic region):
    float* rowbufm  = reinterpret_cast<float*>(smem);          // [4][128]
    float* colbufm  = rowbufm + 512;                           // [2][128]
    float* mrow_sm  = colbufm + 256;                           // [128]
    float* mcol_sm  = mrow_sm + 128;                           // [128]
    float* rowbuf_n = mcol_sm + 128;                           // [4][128]
    float* colbuf_n = rowbuf_n + 512;                          // [2][128]
    float* rowbuf_p = colbuf_n + 256;                          // [4][128]
    float* colbuf_p = rowbuf_p + 512;                          // [2][128]

    // ---- P0: positive maxima per (row,tile) / (col,tile) — no exp --------
    {
        float rmax[4][2], cmax[4][2];
        #pragma unroll
        for (int a = 0; a < 4; a++) {
            rmax[a][0] = rmax[a][1] = NEG_INF;
            cmax[a][0] = cmax[a][1] = NEG_INF;
        }
        #pragma unroll
        for (int am = 0; am < 4; am++) {
            int r0 = lr_base + am * 16 + (lane >> 2);
            #pragma unroll
            for (int an = 0; an < 4; an++) {
                int c0 = lc_base + an * 8 + (lane & 3) * 2;
                #pragma unroll
                for (int e = 0; e < 4; e++) {
                    int rr = r0 + (e >> 1) * 8;
                    int cc = c0 + (e & 1);
                    if (sh_tr[rr] == sh_tc[cc] && !(diag && rr == cc)) {
                        float s = acc[am][an][e];
                        float lp = -fmaxf(1.25f - s, 0.f) * (s - 0.75f) * 64.f;
                        rmax[am][e >> 1] = fmaxf(rmax[am][e >> 1], lp);
                        cmax[an][e & 1]  = fmaxf(cmax[an][e & 1], lp);
                    }
                }
            }
        }
        #pragma unroll
        for (int am = 0; am < 4; am++)
            #pragma unroll
            for (int t = 0; t < 2; t++) {
                float v = rmax[am][t];
                v = fmaxf(v, __shfl_xor_sync(0xffffffffu, v, 1));
                v = fmaxf(v, __shfl_xor_sync(0xffffffffu, v, 2));
                if ((lane & 3) == 0)
                    rowbufm[warp_n * 128 + lr_base + am * 16 + t * 8 + (lane >> 2)] = v;
            }
        #pragma unroll
        for (int an = 0; an < 4; an++)
            #pragma unroll
            for (int c = 0; c < 2; c++) {
                float v = cmax[an][c];
                v = fmaxf(v, __shfl_xor_sync(0xffffffffu, v, 4));
                v = fmaxf(v, __shfl_xor_sync(0xffffffffu, v, 8));
                v = fmaxf(v, __shfl_xor_sync(0xffffffffu, v, 16));
                if (lane < 4)
                    colbufm[warp_m * 128 + lc_base + an * 8 + lane * 2 + c] = v;
            }
    }
    __syncthreads();
    if (tid < 128) {
        mrow_sm[tid] = fmaxf(fmaxf(rowbufm[tid], rowbufm[128 + tid]),
                             fmaxf(rowbufm[256 + tid], rowbufm[384 + tid]));
        mcol_sm[tid] = fmaxf(colbufm[tid], colbufm[128 + tid]);
    }
    __syncthreads();

    // ---- P1: fused single sweep — neg sums (fixed max 60) + pos sums ------
    {
        float rsum[4][2], csum[4][2], rps[4][2], cps[4][2];
        #pragma unroll
        for (int a = 0; a < 4; a++) {
            rsum[a][0] = rsum[a][1] = 0.f;
            csum[a][0] = csum[a][1] = 0.f;
            rps[a][0] = rps[a][1] = 0.f;
            cps[a][0] = cps[a][1] = 0.f;
        }
        #pragma unroll
        for (int am = 0; am < 4; am++) {
            int r0 = lr_base + am * 16 + (lane >> 2);
            #pragma unroll
            for (int an = 0; an < 4; an++) {
                int c0 = lc_base + an * 8 + (lane & 3) * 2;
                #pragma unroll
                for (int e = 0; e < 4; e++) {
                    int rr = r0 + (e >> 1) * 8;
                    int cc = c0 + (e & 1);
                    float s = acc[am][an][e];
                    bool same = (sh_tr[rr] == sh_tc[cc]);
                    if (!same) {
                        float ex = __expf(fmaxf(s + 0.25f, 0.f) * (s - 0.25f) * 64.f - 60.f);
                        rsum[am][e >> 1] += ex;
                        csum[an][e & 1] += ex;
                    } else if (!(diag && rr == cc)) {
                        float lp = -fmaxf(1.25f - s, 0.f) * (s - 0.75f) * 64.f;
                        rps[am][e >> 1] += __expf(lp - mrow_sm[rr]);
                        cps[an][e & 1]  += __expf(lp - mcol_sm[cc]);
                    }
                }
            }
        }
        #pragma unroll
        for (int am = 0; am < 4; am++)
            #pragma unroll
            for (int t = 0; t < 2; t++) {
                float v = rsum[am][t];
                v += __shfl_xor_sync(0xffffffffu, v, 1);
                v += __shfl_xor_sync(0xffffffffu, v, 2);
                float w = rps[am][t];
                w += __shfl_xor_sync(0xffffffffu, w, 1);
                w += __shfl_xor_sync(0xffffffffu, w, 2);
                if ((lane & 3) == 0) {
                    int idx = warp_n * 128 + lr_base + am * 16 + t * 8 + (lane >> 2);
                    rowbuf_n[idx] = v;
                    rowbuf_p[idx] = w;
                }
            }
        #pragma unroll
        for (int an = 0; an < 4; an++)
            #pragma unroll
            for (int c = 0; c < 2; c++) {
                float v = csum[an][c];
                v += __shfl_xor_sync(0xffffffffu, v, 4);
                v += __shfl_xor_sync(0xffffffffu, v, 8);
                v += __shfl_xor_sync(0xffffffffu, v, 16);
                float w = cps[an][c];
                w += __shfl_xor_sync(0xffffffffu, w, 4);
                w += __shfl_xor_sync(0xffffffffu, w, 8);
                w += __shfl_xor_sync(0xffffffffu, w, 16);
                if (lane < 4) {
                    int idx = warp_m * 128 + lc_base + an * 8 + lane * 2 + c;
                    colbuf_n[idx] = v;
                    colbuf_p[idx] = w;
                }
            }
    }
    __syncthreads();
    if (tid < 128) {
        float sn = rowbuf_n[tid] + rowbuf_n[128 + tid] +
                   rowbuf_n[256 + tid] + rowbuf_n[384 + tid];
        g_part_n[(size_t)(rm + tid) * NT + bx] = sn;
        float sp = rowbuf_p[tid] + rowbuf_p[128 + tid] +
                   rowbuf_p[256 + tid] + rowbuf_p[384 + tid];
        g_part_ps[(size_t)(rm + tid) * NT + bx] = sp;
        g_part_pm[(size_t)(rm + tid) * NT + bx] = mrow_sm[tid];
        if (bx > by) {
            g_part_n[(size_t)(cn + tid) * NT + by] = colbuf_n[tid] + colbuf_n[128 + tid];
            g_part_ps[(size_t)(cn + tid) * NT + by] = colbuf_p[tid] + colbuf_p[128 + tid];
            g_part_pm[(size_t)(cn + tid) * NT + by] = mcol_sm[tid];
        }
    }
}

// ---------------------------------------------------------------------------
// Kernel 3: per-row combine — one WARP per row. Neg: plain sum. Pos: online
// (m,s) merge of 64 pairs. Deterministic fixed order.
// ---------------------------------------------------------------------------
__global__ __launch_bounds__(256) void rowlse_k() {
    int row = blockIdx.x * 8 + (threadIdx.x >> 5);
    int lane = threadIdx.x & 31;

    float2 nv = reinterpret_cast<const float2*>(g_part_n + (size_t)row * NT)[lane];
    float sn = nv.x + nv.y;
    #pragma unroll
    for (int o = 16; o; o >>= 1) sn += __shfl_xor_sync(0xffffffffu, sn, o);

    float2 mv = reinterpret_cast<const float2*>(g_part_pm + (size_t)row * NT)[lane];
    float2 sv = reinterpret_cast<const float2*>(g_part_ps + (size_t)row * NT)[lane];
    float m = fmaxf(mv.x, mv.y);
    float s = sv.x * __expf(mv.x - m) + sv.y * __expf(mv.y - m);
    #pragma unroll
    for (int o = 16; o; o >>= 1) {
        float mo = __shfl_xor_sync(0xffffffffu, m, o);
        float so = __shfl_xor_sync(0xffffffffu, s, o);
        float mm = fmaxf(m, mo);
        s = s * __expf(m - mm) + so * __expf(mo - mm);
        m = mm;
    }

    if (lane == 0) {
        int t = g_tgt[row];
        int c = ((unsigned)t < 512u) ? g_hist[t] : 0;
        int valid = (c >= 2) && (c < NB);
        float loss = 0.f;
        if (valid) {
            sn = fmaxf(sn, 1e-37f);
            s = fmaxf(s, 1e-37f);
            float x = 60.f + logf(sn) + m + logf(s);
            loss = fmaxf(x, 0.f) + log1pf(expf(-fabsf(x)));
        }
        g_loss[row] = loss;
    }
}

// ---------------------------------------------------------------------------
// Kernel 4: deterministic final reduction (validity from histogram).
// ---------------------------------------------------------------------------
__global__ __launch_bounds__(1024) void finalize_k(float* __restrict__ out) {
    __shared__ float sh_s[1024];
    __shared__ int sh_c[1024];
    int tid = threadIdx.x;
    float t = 0.f;
    int c = 0;
    for (int r = tid; r < NB; r += 1024) {
        t += g_loss[r];
        int tv = g_tgt[r];
        int cnt = ((unsigned)tv < 512u) ? g_hist[tv] : 0;
        c += ((cnt >= 2) && (cnt < NB)) ? 1 : 0;
    }
    sh_s[tid] = t; sh_c[tid] = c;
    __syncthreads();
    for (int off = 512; off > 0; off >>= 1) {
        if (tid < off) {
            sh_s[tid] += sh_s[tid + off];
            sh_c[tid] += sh_c[tid + off];
        }
        __syncthreads();
    }
    if (tid == 0) {
        int cnt = sh_c[0] > 1 ? sh_c[0] : 1;
        out[0] = sh_s[0] / (float)cnt;
    }
}

// ---------------------------------------------------------------------------
extern "C" void kernel_launch(void* const* d_in, const int* in_sizes, int n_in,
                              void* d_out, int out_size) {
    const float* x = (const float*)d_in[0];
    const void* tg = d_in[1];
    float* out = (float*)d_out;

    cudaFuncSetAttribute(gemm_k, cudaFuncAttributeMaxDynamicSharedMemorySize,
                         3 * 2 * STAGE_BYTES);

    detect_k<<<1, 512>>>((const int*)tg);
    normalize_k<<<NB, 256>>>(x, tg);
    gemm_k<<<dim3(NT, NT), 256, 3 * 2 * STAGE_BYTES>>>();
    rowlse_k<<<NB / 8, 256>>>();
    finalize_k<<<1, 1024>>>(out);
}